// round 1
// baseline (speedup 1.0000x reference)
#include <cuda_runtime.h>
#include <stdint.h>

// WeightedHashEmbedding:
//   out[b, d] = (1/32) * sum_{c=0..31} table[idx0[b,c], d] * weights[idx1[b,c]]
// table:   [1048576, 64] f32
// weights: [1048576*64, 1] f32
// idx0:    [32768, 32] i32
// idx1:    [32768, 32] i32
// out:     [32768, 64] f32

#define B_ROWS   32768
#define N_CHUNKS 32
#define DIM      64

__global__ void __launch_bounds__(256)
whe_kernel(const float* __restrict__ table,
           const float* __restrict__ weights,
           const int*   __restrict__ idx0,
           const int*   __restrict__ idx1,
           float2*      __restrict__ out)
{
    const int warps_per_block = blockDim.x >> 5;
    const int b    = blockIdx.x * warps_per_block + (threadIdx.x >> 5);
    const int lane = threadIdx.x & 31;
    if (b >= B_ROWS) return;

    // Coalesced index preload: lane c holds chunk c's indices.
    const int i0 = idx0[b * N_CHUNKS + lane];
    const int i1 = idx1[b * N_CHUNKS + lane];

    float2 acc = make_float2(0.0f, 0.0f);

    #pragma unroll
    for (int c = 0; c < N_CHUNKS; ++c) {
        const int t = __shfl_sync(0xffffffffu, i0, c);
        const int w = __shfl_sync(0xffffffffu, i1, c);
        const float  wv = __ldg(weights + (size_t)w);
        const float2 v  = __ldg(((const float2*)(table + (size_t)t * DIM)) + lane);
        acc.x = fmaf(v.x, wv, acc.x);
        acc.y = fmaf(v.y, wv, acc.y);
    }

    acc.x *= (1.0f / N_CHUNKS);
    acc.y *= (1.0f / N_CHUNKS);
    out[b * 32 + lane] = acc;
}

extern "C" void kernel_launch(void* const* d_in, const int* in_sizes, int n_in,
                              void* d_out, int out_size)
{
    const float* table   = (const float*)d_in[0];
    const float* weights = (const float*)d_in[1];
    const int*   idx0    = (const int*)d_in[2];
    const int*   idx1    = (const int*)d_in[3];
    float2*      out     = (float2*)d_out;

    const int threads = 256;                       // 8 warps -> 8 rows / block
    const int blocks  = B_ROWS / (threads / 32);   // 4096
    whe_kernel<<<blocks, threads>>>(table, weights, idx0, idx1, out);
}

// round 3
// speedup vs baseline: 1.0354x; 1.0354x over previous
#include <cuda_runtime.h>
#include <stdint.h>

// WeightedHashEmbedding:
//   out[b, d] = (1/32) * sum_{c=0..31} table[idx0[b,c], d] * weights[idx1[b,c]]
// table:   [1048576, 64] f32   (256 MB — keep in L2: evict_last via policy reg)
// weights: [1048576*64] f32    (random 32B sectors, zero reuse: __ldcs streaming)
// idx0/1:  [32768, 32] i32
// out:     [32768, 64] f32

#define B_ROWS   32768
#define N_CHUNKS 32
#define DIM      64

// Create an L2 evict_last cache policy once per thread.
__device__ __forceinline__ uint64_t mk_evict_last_policy() {
    uint64_t pol;
    asm volatile("createpolicy.fractional.L2::evict_last.b64 %0, 1.0;"
                 : "=l"(pol));
    return pol;
}

// Table rows: keep resident in L2 (repeats ~37% of the 1M accesses).
__device__ __forceinline__ float2 ldg_table(const float2* p, uint64_t pol) {
    float2 v;
    asm volatile("ld.global.nc.L2::cache_hint.v2.f32 {%0,%1}, [%2], %3;"
                 : "=f"(v.x), "=f"(v.y) : "l"(p), "l"(pol));
    return v;
}

__global__ void __launch_bounds__(256)
whe_kernel(const float* __restrict__ table,
           const float* __restrict__ weights,
           const int*   __restrict__ idx0,
           const int*   __restrict__ idx1,
           float2*      __restrict__ out)
{
    const int warps_per_block = blockDim.x >> 5;
    const int b    = blockIdx.x * warps_per_block + (threadIdx.x >> 5);
    const int lane = threadIdx.x & 31;
    if (b >= B_ROWS) return;

    // Coalesced index preload: lane c holds chunk c's indices.
    const int i0 = idx0[b * N_CHUNKS + lane];
    const int i1 = idx1[b * N_CHUNKS + lane];

    // Prefetch ALL 32 weights up front with one divergent streaming load
    // (same sector traffic, but off the loop's critical path; evict-first
    // semantics keep these one-shot sectors from polluting L2).
    const float wv_lane = __ldcs(weights + (uint32_t)i1);

    const uint64_t pol = mk_evict_last_policy();

    float2 acc = make_float2(0.0f, 0.0f);

    #pragma unroll
    for (int c = 0; c < N_CHUNKS; ++c) {
        const int   t  = __shfl_sync(0xffffffffu, i0, c);
        const float wv = __shfl_sync(0xffffffffu, wv_lane, c);
        const float2 v = ldg_table(((const float2*)(table + (size_t)t * DIM)) + lane, pol);
        acc.x = fmaf(v.x, wv, acc.x);
        acc.y = fmaf(v.y, wv, acc.y);
    }

    acc.x *= (1.0f / N_CHUNKS);
    acc.y *= (1.0f / N_CHUNKS);
    out[b * 32 + lane] = acc;
}

extern "C" void kernel_launch(void* const* d_in, const int* in_sizes, int n_in,
                              void* d_out, int out_size)
{
    const float* table   = (const float*)d_in[0];
    const float* weights = (const float*)d_in[1];
    const int*   idx0    = (const int*)d_in[2];
    const int*   idx1    = (const int*)d_in[3];
    float2*      out     = (float2*)d_out;

    const int threads = 256;                       // 8 warps -> 8 rows / block
    const int blocks  = B_ROWS / (threads / 32);   // 4096
    whe_kernel<<<blocks, threads>>>(table, weights, idx0, idx1, out);
}